// round 13
// baseline (speedup 1.0000x reference)
#include <cuda_runtime.h>

// CalibrationLayer R13: deep-MLP streamer (4-iteration batches, 64-reg budget)
// + R12 shared-search build.
//
//  k1 build_pack: block stages ri (16KB) in shared; thread-per-bucket binary
//     searches in shared; packs rec(b)=(qy<<16)|(qy(b+1)-qy(b)) -> g_tab.
//  k2 calib_main: CTA copies g_tab (57KB) to shared. Hot loop processes FOUR
//     grid-stride slots per step: 4 LDG.128 issued first, then 16 independent
//     LDS.32 evals, then 4 STG.128. 512 thr x 2 CTAs/SM, 64 regs/thread
//     (whole RF) -> per-SM in-flight = 32 warps x 4 = 128 (R11 best was 96).
// Accuracy: chord dev ~5e-6 + quant 8e-6 abs << 1e-3; fb-clamp gives exact
// end-clamps (edge values = ro endpoints).

#define KBUCK   14336
#define QS      65535.0f
#define QINV    (1.0f / 65535.0f)
#define RMAX    4096

#define BUILD_THREADS 512

#define MAIN_THREADS 512
#define MAIN_CTAS    2
#define MAIN_GRID    (148 * MAIN_CTAS)
#define SMEM_BYTES   (KBUCK * 4)

__device__ unsigned int g_tab[KBUCK];

// ---- kernel 1: build + pack, binary search in shared ----
__global__ __launch_bounds__(BUILD_THREADS)
void build_pack(const float* __restrict__ ri,
                const float* __restrict__ ro, int R) {
    __shared__ float sri[RMAX];
    const int rcap = (R < RMAX) ? R : RMAX;
    for (int i = threadIdx.x; i < rcap; i += BUILD_THREADS)
        sri[i] = ri[i];
    __syncthreads();

    const float lo = sri[0];
    const float hi = sri[R - 1];
    const float w  = (hi - lo) / (float)KBUCK;

    auto edge_val = [&](int e) -> float {
        float ex = fmaf((float)e, w, lo);
        int a = 0, b = R - 1;
        while (b - a > 1) {
            int m = (a + b) >> 1;
            if (sri[m] <= ex) a = m; else b = m;
        }
        float xt = sri[a], xp = sri[a + 1];
        float yt = __ldg(ro + a), yp = __ldg(ro + a + 1);
        return yt + (yp - yt) * __fdividef(ex - xt, xp - xt);
    };

    int bk = blockIdx.x * BUILD_THREADS + threadIdx.x;
    if (bk < KBUCK) {
        float yl = edge_val(bk);
        float yh = edge_val(bk + 1);
        int ql = min(max(__float2int_rn(yl * QS), 0), 65535);
        int qh = min(max(__float2int_rn(yh * QS), 0), 65535);
        g_tab[bk] = ((unsigned int)ql << 16) | (unsigned int)(qh - ql);
    }
}

// ---- kernel 2: streamer ----
extern __shared__ unsigned int tb[];

__global__ __launch_bounds__(MAIN_THREADS, MAIN_CTAS)
void calib_main(const float* __restrict__ x,
                const float* __restrict__ ri,
                float* __restrict__ out,
                int n, int R) {
    // cooperative table load (coalesced, L2-hot)
    {
        const uint4* __restrict__ src = (const uint4*)g_tab;
        uint4* __restrict__ dst = (uint4*)tb;
        #pragma unroll
        for (int k = 0; k < KBUCK / 4 / MAIN_THREADS; ++k)
            dst[k * MAIN_THREADS + threadIdx.x] = src[k * MAIN_THREADS + threadIdx.x];
    }
    __syncthreads();

    const float lo   = __ldg(&ri[0]);
    const float hi   = __ldg(&ri[R - 1]);
    const float invw = (float)KBUCK / (hi - lo);
    const float nglo = -lo * invw;
    const float fK   = (float)KBUCK;

    auto eval = [&](float xv) -> float {
        float fb = fmaf(xv, invw, nglo);
        fb = fminf(fmaxf(fb, 0.0f), fK);          // exact end-clamps
        int b = (int)fb;
        b = min(b, KBUCK - 1);
        unsigned int rec = tb[b];                 // LDS.32
        float frac = fb - (float)b;
        float qy = (float)(rec >> 16);
        float qd = (float)(rec & 0xFFFFu);
        return fmaf(qd, frac, qy) * QINV;
    };

    const int n4 = n >> 2;
    const int s  = MAIN_GRID * MAIN_THREADS;
    const float4* __restrict__ x4 = (const float4*)x;
    float4* __restrict__ o4 = (float4*)out;

    int i = blockIdx.x * MAIN_THREADS + threadIdx.x;

    // 4-slot batches: 4 LDG.128 -> 16 independent LDS.32 -> 4 STG.128
    for (; i + 3 * s < n4; i += 4 * s) {
        float4 v0 = x4[i];
        float4 v1 = x4[i + s];
        float4 v2 = x4[i + 2 * s];
        float4 v3 = x4[i + 3 * s];
        float4 o0, o1, o2, o3;
        o0.x = eval(v0.x); o0.y = eval(v0.y); o0.z = eval(v0.z); o0.w = eval(v0.w);
        o1.x = eval(v1.x); o1.y = eval(v1.y); o1.z = eval(v1.z); o1.w = eval(v1.w);
        o2.x = eval(v2.x); o2.y = eval(v2.y); o2.z = eval(v2.z); o2.w = eval(v2.w);
        o3.x = eval(v3.x); o3.y = eval(v3.y); o3.z = eval(v3.z); o3.w = eval(v3.w);
        o4[i]         = o0;
        o4[i + s]     = o1;
        o4[i + 2 * s] = o2;
        o4[i + 3 * s] = o3;
    }
    for (; i < n4; i += s) {                      // remainder slots
        float4 v = x4[i];
        float4 o;
        o.x = eval(v.x); o.y = eval(v.y); o.z = eval(v.z); o.w = eval(v.w);
        o4[i] = o;
    }

    const int base = n4 << 2;                     // tail (n % 4)
    if (blockIdx.x == 0) {
        for (int j = base + threadIdx.x; j < n; j += MAIN_THREADS)
            out[j] = eval(x[j]);
    }
}

extern "C" void kernel_launch(void* const* d_in, const int* in_sizes, int n_in,
                              void* d_out, int out_size) {
    const float* x  = (const float*)d_in[0];
    const float* ri = (const float*)d_in[1];
    const float* ro = (const float*)d_in[2];
    float* out      = (float*)d_out;
    const int n = in_sizes[0];
    const int R = in_sizes[1];

    build_pack<<<KBUCK / BUILD_THREADS, BUILD_THREADS>>>(ri, ro, R);
    cudaFuncSetAttribute(calib_main, cudaFuncAttributeMaxDynamicSharedMemorySize,
                         SMEM_BYTES);
    calib_main<<<MAIN_GRID, MAIN_THREADS, SMEM_BYTES>>>(x, ri, out, n, R);
}